// round 11
// baseline (speedup 1.0000x reference)
#include <cuda_runtime.h>
#include <math.h>
#include <float.h>
#include <stdint.h>

#define NTOK  16384
#define BSZ   4
#define SEQ   4096
#define DIM   2048
#define NEXP  64
#define TOPK  8
#define BM    64     // tokens per block
#define KC    64     // K chunk width (floats)
#define NTHREADS 128
#define XSS   68     // xs row stride in floats (272B, 16B-aligned)
#define WK4   69     // wq4 k4-stride in float4 (odd mod 8 -> conflict-free stores)
#define WJ4   17     // wq4 j-stride in float4

#define FTZ_MIN 1.17549435e-38f   // FLT_MIN: fp32 normal threshold (FTZ cutoff)

__device__ float g_cnt[BSZ * NEXP];
__device__ float g_ssum[BSZ * NEXP];

__global__ void gate_zero() {
    int i = threadIdx.x;
    if (i < BSZ * NEXP) { g_cnt[i] = 0.f; g_ssum[i] = 0.f; }
}

// Packed fp32x2 FMA. "+l" keeps the accumulator in-place (no MOV churn).
// Each 32-bit lane is an exact IEEE fp32 RN fused FMA -> per-token chains
// are bitwise identical to scalar fmaf chains.
__device__ __forceinline__ void ffma2(unsigned long long& d,
                                      unsigned long long a, unsigned long long b) {
    asm("fma.rn.f32x2 %0, %1, %2, %0;" : "+l"(d) : "l"(a), "l"(b));
}

__device__ __forceinline__ unsigned long long pk2(float lo, float hi) {
    unsigned long long r;
    asm("mov.b64 %0, {%1, %2};" : "=l"(r) : "f"(lo), "f"(hi));
    return r;
}

__global__ __launch_bounds__(NTHREADS) void gate_main(
    const float* __restrict__ x, const float* __restrict__ w,
    const float* __restrict__ bias, float* __restrict__ out)
{
    __shared__ float  xs[BM * XSS];            // [token][k]  17408 B
    __shared__ float4 wq4[(KC / 4) * WK4];     // [k4][j][et] 17664 B
    __shared__ float  lg[BM][NEXP + 1];        //             16640 B
    __shared__ float  s_max[BM];
    __shared__ float  s_inv[BM];
    __shared__ float  s_cnt[NEXP];

    const int tid = threadIdx.x;
    const int et  = tid & 15;   // experts et*4 .. et*4+3
    const int tt  = tid >> 4;   // tokens  tt*8 .. tt*8+7
    const int base = blockIdx.x * BM;

    // packed accumulators: token-pair p = (2p, 2p+1), expert j.  0ULL == (0.f,0.f)
    unsigned long long acc2[4][4];
    #pragma unroll
    for (int p = 0; p < 4; p++)
        #pragma unroll
        for (int j = 0; j < 4; j++) acc2[p][j] = 0ULL;

    const float* xb = x + (size_t)base * DIM;

    for (int kc = 0; kc < DIM; kc += KC) {
        // cooperative load (identical to round-10 proven layout)
        #pragma unroll
        for (int it = 0; it < 8; it++) {
            int idx = tid + it * NTHREADS;     // 0..1023 float4 slots
            int r = idx >> 4;                  // row 0..63
            int c = (idx & 15) << 2;           // k offset 0..60
            float4 v = *(const float4*)(xb + (size_t)r * DIM + kc + c);
            *(float4*)&xs[r * XSS + c] = v;
            float4 u = *(const float4*)(w + (size_t)r * DIM + kc + c);
            wq4[(c >> 2) * WK4 + (r & 3) * WJ4 + (r >> 2)] = u;
        }
        __syncthreads();

        // K strictly ascending per accumulator lane (x->y->z->w)
        #pragma unroll 2
        for (int k4 = 0; k4 < KC / 4; k4++) {
            float4 wv[4];
            #pragma unroll
            for (int j = 0; j < 4; j++)
                wv[j] = wq4[k4 * WK4 + j * WJ4 + et];
            float4 xv[8];
            #pragma unroll
            for (int i = 0; i < 8; i++)
                xv[i] = *(const float4*)&xs[(tt * 8 + i) * XSS + k4 * 4];

            {   // k = k4*4 + 0
                unsigned long long wd0 = pk2(wv[0].x, wv[0].x), wd1 = pk2(wv[1].x, wv[1].x);
                unsigned long long wd2 = pk2(wv[2].x, wv[2].x), wd3 = pk2(wv[3].x, wv[3].x);
                #pragma unroll
                for (int p = 0; p < 4; p++) {
                    unsigned long long xp = pk2(xv[2*p].x, xv[2*p+1].x);
                    ffma2(acc2[p][0], xp, wd0); ffma2(acc2[p][1], xp, wd1);
                    ffma2(acc2[p][2], xp, wd2); ffma2(acc2[p][3], xp, wd3);
                }
            }
            {   // k + 1
                unsigned long long wd0 = pk2(wv[0].y, wv[0].y), wd1 = pk2(wv[1].y, wv[1].y);
                unsigned long long wd2 = pk2(wv[2].y, wv[2].y), wd3 = pk2(wv[3].y, wv[3].y);
                #pragma unroll
                for (int p = 0; p < 4; p++) {
                    unsigned long long xp = pk2(xv[2*p].y, xv[2*p+1].y);
                    ffma2(acc2[p][0], xp, wd0); ffma2(acc2[p][1], xp, wd1);
                    ffma2(acc2[p][2], xp, wd2); ffma2(acc2[p][3], xp, wd3);
                }
            }
            {   // k + 2
                unsigned long long wd0 = pk2(wv[0].z, wv[0].z), wd1 = pk2(wv[1].z, wv[1].z);
                unsigned long long wd2 = pk2(wv[2].z, wv[2].z), wd3 = pk2(wv[3].z, wv[3].z);
                #pragma unroll
                for (int p = 0; p < 4; p++) {
                    unsigned long long xp = pk2(xv[2*p].z, xv[2*p+1].z);
                    ffma2(acc2[p][0], xp, wd0); ffma2(acc2[p][1], xp, wd1);
                    ffma2(acc2[p][2], xp, wd2); ffma2(acc2[p][3], xp, wd3);
                }
            }
            {   // k + 3
                unsigned long long wd0 = pk2(wv[0].w, wv[0].w), wd1 = pk2(wv[1].w, wv[1].w);
                unsigned long long wd2 = pk2(wv[2].w, wv[2].w), wd3 = pk2(wv[3].w, wv[3].w);
                #pragma unroll
                for (int p = 0; p < 4; p++) {
                    unsigned long long xp = pk2(xv[2*p].w, xv[2*p+1].w);
                    ffma2(acc2[p][0], xp, wd0); ffma2(acc2[p][1], xp, wd1);
                    ffma2(acc2[p][2], xp, wd2); ffma2(acc2[p][3], xp, wd3);
                }
            }
        }
        __syncthreads();
    }

    // unpack + bias -> logits smem
    #pragma unroll
    for (int p = 0; p < 4; p++) {
        int row = tt * 8 + p * 2;
        #pragma unroll
        for (int j = 0; j < 4; j++) {
            int col = et * 4 + j;
            float b  = bias[col];
            float lo = __uint_as_float((unsigned)(acc2[p][j] & 0xFFFFFFFFull));
            float hi = __uint_as_float((unsigned)(acc2[p][j] >> 32));
            lg[row    ][col] = lo + b;
            lg[row + 1][col] = hi + b;
        }
    }
    if (tid < NEXP) s_cnt[tid] = 0.f;
    __syncthreads();

    // per-token softmax (FTZ) + top-8 on SCORES, ties -> lower index (lax.top_k)
    if (tid < BM) {
        const int t = tid;
        float m = -FLT_MAX;
        for (int e = 0; e < NEXP; e++) m = fmaxf(m, lg[t][e]);

        float sum = 0.f;
        for (int e = 0; e < NEXP; e++) {
            float s = expf(lg[t][e] - m);
            if (s < FTZ_MIN) s = 0.f;
            sum += s;
        }
        float inv_sum = 1.f / sum;

        float bv[TOPK]; int bi[TOPK];
        #pragma unroll
        for (int r = 0; r < TOPK; r++) { bv[r] = -FLT_MAX; bi[r] = 0; }

        for (int e = 0; e < NEXP; e++) {
            float s = expf(lg[t][e] - m);
            if (s < FTZ_MIN) s = 0.f;
            float q = s * inv_sum;
            if (q < FTZ_MIN) q = 0.f;
            if (q > bv[TOPK - 1]) {
                int p = TOPK - 1;
                while (p > 0 && q > bv[p - 1]) {
                    bv[p] = bv[p - 1]; bi[p] = bi[p - 1]; p--;
                }
                bv[p] = q; bi[p] = e;
            }
        }
        s_max[t] = m;
        s_inv[t] = inv_sum;

        float den = 1e-20f;
        #pragma unroll
        for (int r = 0; r < TOPK; r++) den += bv[r];
        float inv = 1.f / den;

        const int token = base + t;
        #pragma unroll
        for (int r = 0; r < TOPK; r++)
            out[(size_t)token * TOPK + r] = (float)bi[r];
        #pragma unroll
        for (int r = 0; r < TOPK; r++)
            out[(size_t)NTOK * TOPK + (size_t)token * TOPK + r] = bv[r] * inv;
        #pragma unroll
        for (int r = 0; r < TOPK; r++)
            atomicAdd(&s_cnt[bi[r]], 1.f);
    }
    __syncthreads();

    // per-expert column sums of (flushed) softmax scores over this block's tokens
    if (tid < NEXP) {
        const int e = tid;
        float cs = 0.f;
        for (int t = 0; t < BM; t++) {
            float s = expf(lg[t][e] - s_max[t]);
            if (s < FTZ_MIN) s = 0.f;
            float q = s * s_inv[t];
            if (q < FTZ_MIN) q = 0.f;
            cs += q;
        }
        const int b = base / SEQ;
        atomicAdd(&g_ssum[b * NEXP + e], cs);
        atomicAdd(&g_cnt[b * NEXP + e], s_cnt[e]);
    }
}

__global__ void gate_finalize(float* __restrict__ out) {
    __shared__ float red[256];
    const int i = threadIdx.x;
    // aux = mean_b sum_e (cnt/(SEQ*K/E)) * (ssum/SEQ)
    float v = (g_cnt[i] * (1.f / 512.f)) * (g_ssum[i] * (1.f / 4096.f));
    red[i] = v;
    __syncthreads();
    for (int s = 128; s > 0; s >>= 1) {
        if (i < s) red[i] += red[i + s];
        __syncthreads();
    }
    if (i == 0) out[2 * NTOK * TOPK] = red[0] * (1.f / BSZ);
}

extern "C" void kernel_launch(void* const* d_in, const int* in_sizes, int n_in,
                              void* d_out, int out_size) {
    const float* x    = (const float*)d_in[0];   // [4,4096,2048] f32
    const float* wgt  = (const float*)d_in[1];   // [64,2048]     f32
    const float* bias = (const float*)d_in[2];   // [64]          f32
    float* out = (float*)d_out;                  // [idx 131072][w 131072][aux 1]

    gate_zero<<<1, 256>>>();
    gate_main<<<NTOK / BM, NTHREADS>>>(x, wgt, bias, out);
    gate_finalize<<<1, 256>>>(out);
}

// round 12
// speedup vs baseline: 1.0665x; 1.0665x over previous
#include <cuda_runtime.h>
#include <math.h>
#include <float.h>
#include <stdint.h>

#define NTOK  16384
#define BSZ   4
#define SEQ   4096
#define DIM   2048
#define NEXP  64
#define TOPK  8
#define BM    16     // tokens per block (quantization: busiest SM = 7 tiles = 112 tok)
#define KC    64     // K chunk width (floats)
#define NTHREADS 128
#define XSS   68     // xs row stride in floats (272B, 16B-aligned)
#define WK4   69     // wq4 k4-stride in float4 (odd mod 8 -> conflict-free stores)
#define WJ4   17     // wq4 j-stride in float4

#define FTZ_MIN 1.17549435e-38f   // FLT_MIN: fp32 normal threshold (FTZ cutoff)

__device__ float g_cnt[BSZ * NEXP];
__device__ float g_ssum[BSZ * NEXP];

__global__ void gate_zero() {
    int i = threadIdx.x;
    if (i < BSZ * NEXP) { g_cnt[i] = 0.f; g_ssum[i] = 0.f; }
}

__global__ __launch_bounds__(NTHREADS) void gate_main(
    const float* __restrict__ x, const float* __restrict__ w,
    const float* __restrict__ bias, float* __restrict__ out)
{
    __shared__ float  xs[BM * XSS];            // [token][k]   4352 B
    __shared__ float4 wq4[(KC / 4) * WK4];     // [k4][j][et] 17664 B
    __shared__ float  lg[BM][NEXP + 1];        //              4160 B
    __shared__ float  s_max[BM];
    __shared__ float  s_inv[BM];
    __shared__ float  s_cnt[NEXP];

    const int tid = threadIdx.x;
    const int et  = tid & 15;   // experts et*4 .. et*4+3
    const int tt  = tid >> 4;   // token pair: tokens tt*2, tt*2+1
    const int base = blockIdx.x * BM;

    float acc[2][4];            // (token i, expert j) — same chains as round 8
    #pragma unroll
    for (int i = 0; i < 2; i++)
        #pragma unroll
        for (int j = 0; j < 4; j++) acc[i][j] = 0.f;

    const float* xb = x + (size_t)base * DIM;

    for (int kc = 0; kc < DIM; kc += KC) {
        // cooperative load: w -> wq4[k4][j][et] (proven layout); x -> xs[row][k]
        #pragma unroll
        for (int it = 0; it < 8; it++) {
            int idx = tid + it * NTHREADS;     // 0..1023 float4 slots
            int r = idx >> 4;                  // w row 0..63
            int c = (idx & 15) << 2;           // k offset 0..60
            float4 u = *(const float4*)(w + (size_t)r * DIM + kc + c);
            wq4[(c >> 2) * WK4 + (r & 3) * WJ4 + (r >> 2)] = u;
        }
        #pragma unroll
        for (int it = 0; it < 2; it++) {
            int idx = tid + it * NTHREADS;     // 0..255 float4 slots
            int r = idx >> 4;                  // x row 0..15
            int c = (idx & 15) << 2;
            float4 v = *(const float4*)(xb + (size_t)r * DIM + kc + c);
            *(float4*)&xs[r * XSS + c] = v;
        }
        __syncthreads();

        // K strictly ascending per accumulator (x->y->z->w): bitwise round-8 chains
        #pragma unroll 4
        for (int k4 = 0; k4 < KC / 4; k4++) {
            float4 wv[4];
            #pragma unroll
            for (int j = 0; j < 4; j++)
                wv[j] = wq4[k4 * WK4 + j * WJ4 + et];
            float4 xv[2];
            #pragma unroll
            for (int i = 0; i < 2; i++)
                xv[i] = *(const float4*)&xs[(tt * 2 + i) * XSS + k4 * 4];

            #pragma unroll
            for (int i = 0; i < 2; i++)
                #pragma unroll
                for (int j = 0; j < 4; j++)
                    acc[i][j] = fmaf(xv[i].x, wv[j].x, acc[i][j]);
            #pragma unroll
            for (int i = 0; i < 2; i++)
                #pragma unroll
                for (int j = 0; j < 4; j++)
                    acc[i][j] = fmaf(xv[i].y, wv[j].y, acc[i][j]);
            #pragma unroll
            for (int i = 0; i < 2; i++)
                #pragma unroll
                for (int j = 0; j < 4; j++)
                    acc[i][j] = fmaf(xv[i].z, wv[j].z, acc[i][j]);
            #pragma unroll
            for (int i = 0; i < 2; i++)
                #pragma unroll
                for (int j = 0; j < 4; j++)
                    acc[i][j] = fmaf(xv[i].w, wv[j].w, acc[i][j]);
        }
        __syncthreads();
    }

    // logits + bias -> smem
    #pragma unroll
    for (int j = 0; j < 4; j++) {
        float b = bias[et * 4 + j];
        #pragma unroll
        for (int i = 0; i < 2; i++)
            lg[tt * 2 + i][et * 4 + j] = acc[i][j] + b;
    }
    if (tid < NEXP) s_cnt[tid] = 0.f;
    __syncthreads();

    // per-token softmax (FTZ) + top-8 on SCORES, ties -> lower index (lax.top_k)
    if (tid < BM) {
        const int t = tid;
        float m = -FLT_MAX;
        for (int e = 0; e < NEXP; e++) m = fmaxf(m, lg[t][e]);

        float sum = 0.f;
        for (int e = 0; e < NEXP; e++) {
            float s = expf(lg[t][e] - m);
            if (s < FTZ_MIN) s = 0.f;
            sum += s;
        }
        float inv_sum = 1.f / sum;

        float bv[TOPK]; int bi[TOPK];
        #pragma unroll
        for (int r = 0; r < TOPK; r++) { bv[r] = -FLT_MAX; bi[r] = 0; }

        for (int e = 0; e < NEXP; e++) {
            float s = expf(lg[t][e] - m);
            if (s < FTZ_MIN) s = 0.f;
            float q = s * inv_sum;
            if (q < FTZ_MIN) q = 0.f;
            if (q > bv[TOPK - 1]) {
                int p = TOPK - 1;
                while (p > 0 && q > bv[p - 1]) {
                    bv[p] = bv[p - 1]; bi[p] = bi[p - 1]; p--;
                }
                bv[p] = q; bi[p] = e;
            }
        }
        s_max[t] = m;
        s_inv[t] = inv_sum;

        float den = 1e-20f;
        #pragma unroll
        for (int r = 0; r < TOPK; r++) den += bv[r];
        float inv = 1.f / den;

        const int token = base + t;
        #pragma unroll
        for (int r = 0; r < TOPK; r++)
            out[(size_t)token * TOPK + r] = (float)bi[r];
        #pragma unroll
        for (int r = 0; r < TOPK; r++)
            out[(size_t)NTOK * TOPK + (size_t)token * TOPK + r] = bv[r] * inv;
        #pragma unroll
        for (int r = 0; r < TOPK; r++)
            atomicAdd(&s_cnt[bi[r]], 1.f);
    }
    __syncthreads();

    // per-expert column sums of (flushed) softmax scores over this block's tokens
    if (tid < NEXP) {
        const int e = tid;
        float cs = 0.f;
        for (int t = 0; t < BM; t++) {
            float s = expf(lg[t][e] - s_max[t]);
            if (s < FTZ_MIN) s = 0.f;
            float q = s * s_inv[t];
            if (q < FTZ_MIN) q = 0.f;
            cs += q;
        }
        const int b = base / SEQ;
        atomicAdd(&g_ssum[b * NEXP + e], cs);
        atomicAdd(&g_cnt[b * NEXP + e], s_cnt[e]);
    }
}

__global__ void gate_finalize(float* __restrict__ out) {
    __shared__ float red[256];
    const int i = threadIdx.x;
    // aux = mean_b sum_e (cnt/(SEQ*K/E)) * (ssum/SEQ)
    float v = (g_cnt[i] * (1.f / 512.f)) * (g_ssum[i] * (1.f / 4096.f));
    red[i] = v;
    __syncthreads();
    for (int s = 128; s > 0; s >>= 1) {
        if (i < s) red[i] += red[i + s];
        __syncthreads();
    }
    if (i == 0) out[2 * NTOK * TOPK] = red[0] * (1.f / BSZ);
}

extern "C" void kernel_launch(void* const* d_in, const int* in_sizes, int n_in,
                              void* d_out, int out_size) {
    const float* x    = (const float*)d_in[0];   // [4,4096,2048] f32
    const float* wgt  = (const float*)d_in[1];   // [64,2048]     f32
    const float* bias = (const float*)d_in[2];   // [64]          f32
    float* out = (float*)d_out;                  // [idx 131072][w 131072][aux 1]

    gate_zero<<<1, 256>>>();
    gate_main<<<NTOK / BM, NTHREADS>>>(x, wgt, bias, out);
    gate_finalize<<<1, 256>>>(out);
}

// round 13
// speedup vs baseline: 1.6913x; 1.5858x over previous
#include <cuda_runtime.h>
#include <math.h>
#include <float.h>
#include <stdint.h>

#define NTOK  16384
#define BSZ   4
#define SEQ   4096
#define DIM   2048
#define NEXP  64
#define TOPK  8
#define BMT   112    // tokens per block; grid = 147 <= 152 SMs -> 1 block/SM
#define KC    64     // K chunk width (floats)
#define NTH   256
#define NBLK  ((NTOK + BMT - 1) / BMT)   // 147
#define XSS   64     // xs row stride (floats)
#define LGS   66     // lg row stride (floats)
#define WK4   69     // wq4 k4-stride in float4 (proven round-10 layout)
#define WJ4   17     // wq4 j-stride in float4

#define FTZ_MIN 1.17549435e-38f   // FLT_MIN: fp32 normal threshold (FTZ cutoff)

__device__ float g_cnt[BSZ * NEXP];
__device__ float g_ssum[BSZ * NEXP];

__global__ void gate_zero() {
    int i = threadIdx.x;
    if (i < BSZ * NEXP) { g_cnt[i] = 0.f; g_ssum[i] = 0.f; }
}

__global__ __launch_bounds__(NTH, 1) void gate_main(
    const float* __restrict__ x, const float* __restrict__ w,
    const float* __restrict__ bias, float* __restrict__ out)
{
    // xs ([112][64] floats, GEMM phase) and lg ([112][66] floats, epilogue) share storage
    __shared__ __align__(16) float regA[BMT * LGS];      // 29568 B
    __shared__ float4 wq4[(KC / 4) * WK4];               // 17664 B
    __shared__ float  s_max[BMT];
    __shared__ float  s_inv[BMT];
    __shared__ float  s_cnt[2 * NEXP];

    float* xs = regA;
    float* lg = regA;

    const int tid = threadIdx.x;
    const int et  = tid & 15;    // experts et*4 .. et*4+3
    const int ts  = tid >> 4;    // token slot: tokens ts*7 .. ts*7+6
    const int base = blockIdx.x * BMT;
    const int nval = min(BMT, NTOK - base);

    float acc[7][4];
    #pragma unroll
    for (int i = 0; i < 7; i++)
        #pragma unroll
        for (int j = 0; j < 4; j++) acc[i][j] = 0.f;

    float4 wr[4], xr[7];

    // ---- prefetch chunk 0 into registers ----
    #pragma unroll
    for (int it = 0; it < 4; it++) {
        int idx = tid + it * NTH;              // 0..1023
        int r = idx >> 4, c = (idx & 15) << 2;
        wr[it] = *(const float4*)(w + (size_t)r * DIM + c);
    }
    #pragma unroll
    for (int it = 0; it < 7; it++) {
        int idx = tid + it * NTH;              // 0..1791
        int r = idx >> 4, c = (idx & 15) << 2;
        int rr = min(base + r, NTOK - 1);      // clamp (last block partial)
        xr[it] = *(const float4*)(x + (size_t)rr * DIM + c);
    }

    for (int kc = 0; kc < DIM; kc += KC) {
        if (kc) __syncthreads();               // prev compute done; smem reusable

        // store prefetched regs -> smem
        #pragma unroll
        for (int it = 0; it < 4; it++) {
            int idx = tid + it * NTH;
            int r = idx >> 4, c = (idx & 15) << 2;
            wq4[(c >> 2) * WK4 + (r & 3) * WJ4 + (r >> 2)] = wr[it];
        }
        #pragma unroll
        for (int it = 0; it < 7; it++) {
            int idx = tid + it * NTH;
            int r = idx >> 4, c = (idx & 15) << 2;
            *(float4*)&xs[r * XSS + c] = xr[it];
        }
        __syncthreads();

        // issue next chunk's loads (land during compute)
        if (kc + KC < DIM) {
            #pragma unroll
            for (int it = 0; it < 4; it++) {
                int idx = tid + it * NTH;
                int r = idx >> 4, c = (idx & 15) << 2;
                wr[it] = *(const float4*)(w + (size_t)r * DIM + kc + KC + c);
            }
            #pragma unroll
            for (int it = 0; it < 7; it++) {
                int idx = tid + it * NTH;
                int r = idx >> 4, c = (idx & 15) << 2;
                int rr = min(base + r, NTOK - 1);
                xr[it] = *(const float4*)(x + (size_t)rr * DIM + kc + KC + c);
            }
        }

        // K strictly ascending per accumulator (x->y->z->w): bitwise-stable chains
        #pragma unroll 2
        for (int k4 = 0; k4 < KC / 4; k4++) {
            float4 wv[4];
            #pragma unroll
            for (int j = 0; j < 4; j++)
                wv[j] = wq4[k4 * WK4 + j * WJ4 + et];
            float4 xv[7];
            #pragma unroll
            for (int i = 0; i < 7; i++)
                xv[i] = *(const float4*)&xs[(ts * 7 + i) * XSS + k4 * 4];

            #pragma unroll
            for (int i = 0; i < 7; i++)
                #pragma unroll
                for (int j = 0; j < 4; j++)
                    acc[i][j] = fmaf(xv[i].x, wv[j].x, acc[i][j]);
            #pragma unroll
            for (int i = 0; i < 7; i++)
                #pragma unroll
                for (int j = 0; j < 4; j++)
                    acc[i][j] = fmaf(xv[i].y, wv[j].y, acc[i][j]);
            #pragma unroll
            for (int i = 0; i < 7; i++)
                #pragma unroll
                for (int j = 0; j < 4; j++)
                    acc[i][j] = fmaf(xv[i].z, wv[j].z, acc[i][j]);
            #pragma unroll
            for (int i = 0; i < 7; i++)
                #pragma unroll
                for (int j = 0; j < 4; j++)
                    acc[i][j] = fmaf(xv[i].w, wv[j].w, acc[i][j]);
        }
    }
    __syncthreads();   // all xs reads done before lg overwrites the union

    // logits + bias -> lg
    #pragma unroll
    for (int j = 0; j < 4; j++) {
        float b = bias[et * 4 + j];
        #pragma unroll
        for (int i = 0; i < 7; i++)
            lg[(ts * 7 + i) * LGS + et * 4 + j] = acc[i][j] + b;
    }
    if (tid < 2 * NEXP) s_cnt[tid] = 0.f;
    __syncthreads();

    const int b0 = base / SEQ;
    const int t_split = min(BMT, (b0 + 1) * SEQ - base);   // batch boundary within block

    // per-token softmax (FTZ) + top-8 on SCORES, ties -> lower index (lax.top_k)
    if (tid < nval) {
        const int t = tid;
        const float* lrow = &lg[t * LGS];
        float m = -FLT_MAX;
        for (int e = 0; e < NEXP; e++) m = fmaxf(m, lrow[e]);

        float sum = 0.f;
        for (int e = 0; e < NEXP; e++) {
            float s = expf(lrow[e] - m);
            if (s < FTZ_MIN) s = 0.f;
            sum += s;
        }
        float inv_sum = 1.f / sum;

        float bv[TOPK]; int bi[TOPK];
        #pragma unroll
        for (int r = 0; r < TOPK; r++) { bv[r] = -FLT_MAX; bi[r] = 0; }

        for (int e = 0; e < NEXP; e++) {
            float s = expf(lrow[e] - m);
            if (s < FTZ_MIN) s = 0.f;
            float q = s * inv_sum;
            if (q < FTZ_MIN) q = 0.f;
            if (q > bv[TOPK - 1]) {
                int p = TOPK - 1;
                while (p > 0 && q > bv[p - 1]) {
                    bv[p] = bv[p - 1]; bi[p] = bi[p - 1]; p--;
                }
                bv[p] = q; bi[p] = e;
            }
        }
        s_max[t] = m;
        s_inv[t] = inv_sum;

        float den = 1e-20f;
        #pragma unroll
        for (int r = 0; r < TOPK; r++) den += bv[r];
        float inv = 1.f / den;

        const int token = base + t;
        const int part  = (t < t_split) ? 0 : 1;
        #pragma unroll
        for (int r = 0; r < TOPK; r++)
            out[(size_t)token * TOPK + r] = (float)bi[r];
        #pragma unroll
        for (int r = 0; r < TOPK; r++)
            out[(size_t)NTOK * TOPK + (size_t)token * TOPK + r] = bv[r] * inv;
        #pragma unroll
        for (int r = 0; r < TOPK; r++)
            atomicAdd(&s_cnt[part * NEXP + bi[r]], 1.f);
    }
    __syncthreads();

    // per-expert column sums of (flushed) softmax scores, split by batch bucket
    if (tid < NEXP) {
        const int e = tid;
        float cs0 = 0.f, cs1 = 0.f;
        for (int t = 0; t < nval; t++) {
            float s = expf(lg[t * LGS + e] - s_max[t]);
            if (s < FTZ_MIN) s = 0.f;
            float q = s * s_inv[t];
            if (q < FTZ_MIN) q = 0.f;
            if (t < t_split) cs0 += q; else cs1 += q;
        }
        atomicAdd(&g_ssum[b0 * NEXP + e], cs0);
        atomicAdd(&g_cnt [b0 * NEXP + e], s_cnt[e]);
        if (t_split < nval) {
            atomicAdd(&g_ssum[(b0 + 1) * NEXP + e], cs1);
            atomicAdd(&g_cnt [(b0 + 1) * NEXP + e], s_cnt[NEXP + e]);
        }
    }
}

__global__ void gate_finalize(float* __restrict__ out) {
    __shared__ float red[256];
    const int i = threadIdx.x;
    // aux = mean_b sum_e (cnt/(SEQ*K/E)) * (ssum/SEQ)
    float v = (g_cnt[i] * (1.f / 512.f)) * (g_ssum[i] * (1.f / 4096.f));
    red[i] = v;
    __syncthreads();
    for (int s = 128; s > 0; s >>= 1) {
        if (i < s) red[i] += red[i + s];
        __syncthreads();
    }
    if (i == 0) out[2 * NTOK * TOPK] = red[0] * (1.f / BSZ);
}

extern "C" void kernel_launch(void* const* d_in, const int* in_sizes, int n_in,
                              void* d_out, int out_size) {
    const float* x    = (const float*)d_in[0];   // [4,4096,2048] f32
    const float* wgt  = (const float*)d_in[1];   // [64,2048]     f32
    const float* bias = (const float*)d_in[2];   // [64]          f32
    float* out = (float*)d_out;                  // [idx 131072][w 131072][aux 1]

    gate_zero<<<1, 256>>>();
    gate_main<<<NBLK, NTH>>>(x, wgt, bias, out);
    gate_finalize<<<1, 256>>>(out);
}

// round 14
// speedup vs baseline: 1.7209x; 1.0175x over previous
#include <cuda_runtime.h>
#include <math.h>
#include <float.h>
#include <stdint.h>

#define NTOK  16384
#define BSZ   4
#define SEQ   4096
#define DIM   2048
#define NEXP  64
#define TOPK  8
#define BMT   108    // tokens per block; grid = 152 = #SMs -> exactly 1 block/SM
#define KC    64     // K chunk width (floats)
#define NTH   256
#define NBLK  ((NTOK + BMT - 1) / BMT)   // 152
#define XSS   64     // xs row stride (floats)
#define LGS   66     // lg row stride (floats)
#define WK4   69     // wq4 k4-stride in float4 (proven layout)
#define WJ4   17     // wq4 j-stride in float4
#define XSLOTS (BMT * 16)                // 1728 float4 slots for x chunk

#define FTZ_MIN 1.17549435e-38f   // FLT_MIN: fp32 normal threshold (FTZ cutoff)

__device__ float g_cnt[BSZ * NEXP];      // zero-init at load; re-zeroed by last block
__device__ float g_ssum[BSZ * NEXP];
__device__ unsigned g_done;

// Inner chunk compute: NT tokens starting at smem row row0, experts et*4..+3.
// K strictly ascending per accumulator (x->y->z->w): bitwise-stable fmaf chains.
template <int NT>
__device__ __forceinline__ void compute_chunk(
    const float* __restrict__ xs, const float4* __restrict__ wq4,
    int et, int row0, float (&acc)[7][4])
{
    #pragma unroll 2
    for (int k4 = 0; k4 < KC / 4; k4++) {
        float4 wv[4];
        #pragma unroll
        for (int j = 0; j < 4; j++)
            wv[j] = wq4[k4 * WK4 + j * WJ4 + et];
        float4 xv[NT];
        #pragma unroll
        for (int i = 0; i < NT; i++)
            xv[i] = *(const float4*)&xs[(row0 + i) * XSS + k4 * 4];

        #pragma unroll
        for (int i = 0; i < NT; i++)
            #pragma unroll
            for (int j = 0; j < 4; j++)
                acc[i][j] = fmaf(xv[i].x, wv[j].x, acc[i][j]);
        #pragma unroll
        for (int i = 0; i < NT; i++)
            #pragma unroll
            for (int j = 0; j < 4; j++)
                acc[i][j] = fmaf(xv[i].y, wv[j].y, acc[i][j]);
        #pragma unroll
        for (int i = 0; i < NT; i++)
            #pragma unroll
            for (int j = 0; j < 4; j++)
                acc[i][j] = fmaf(xv[i].z, wv[j].z, acc[i][j]);
        #pragma unroll
        for (int i = 0; i < NT; i++)
            #pragma unroll
            for (int j = 0; j < 4; j++)
                acc[i][j] = fmaf(xv[i].w, wv[j].w, acc[i][j]);
    }
}

__global__ __launch_bounds__(NTH, 1) void gate_main(
    const float* __restrict__ x, const float* __restrict__ w,
    const float* __restrict__ bias, float* __restrict__ out)
{
    // xs ([108][64], GEMM) and lg ([108][66], epilogue) and red[256] share storage
    __shared__ __align__(16) float regA[BMT * LGS];      // 28512 B
    __shared__ float4 wq4[(KC / 4) * WK4];               // 17664 B
    __shared__ float  s_max[BMT];
    __shared__ float  s_inv[BMT];
    __shared__ float  s_cnt[2 * NEXP];
    __shared__ unsigned s_last;

    float* xs = regA;
    float* lg = regA;

    const int tid = threadIdx.x;
    const int et  = tid & 15;    // experts et*4 .. et*4+3
    const int ts  = tid >> 4;    // token slot
    const int nt  = (ts < 12) ? 7 : 6;
    const int row0 = (ts < 12) ? ts * 7 : 84 + (ts - 12) * 6;   // 12*7 + 4*6 = 108
    const int base = blockIdx.x * BMT;
    const int nval = min(BMT, NTOK - base);

    float acc[7][4];
    #pragma unroll
    for (int i = 0; i < 7; i++)
        #pragma unroll
        for (int j = 0; j < 4; j++) acc[i][j] = 0.f;

    float4 wr[4], xr[7];

    // ---- prefetch chunk 0 into registers ----
    #pragma unroll
    for (int it = 0; it < 4; it++) {
        int idx = tid + it * NTH;
        int r = idx >> 4, c = (idx & 15) << 2;
        wr[it] = *(const float4*)(w + (size_t)r * DIM + c);
    }
    #pragma unroll
    for (int it = 0; it < 7; it++) {
        int idx = tid + it * NTH;
        if (idx < XSLOTS) {
            int r = idx >> 4, c = (idx & 15) << 2;
            int rr = min(base + r, NTOK - 1);
            xr[it] = *(const float4*)(x + (size_t)rr * DIM + c);
        }
    }

    for (int kc = 0; kc < DIM; kc += KC) {
        if (kc) __syncthreads();               // prev compute done; smem reusable

        // store prefetched regs -> smem
        #pragma unroll
        for (int it = 0; it < 4; it++) {
            int idx = tid + it * NTH;
            int r = idx >> 4, c = (idx & 15) << 2;
            wq4[(c >> 2) * WK4 + (r & 3) * WJ4 + (r >> 2)] = wr[it];
        }
        #pragma unroll
        for (int it = 0; it < 7; it++) {
            int idx = tid + it * NTH;
            if (idx < XSLOTS) {
                int r = idx >> 4, c = (idx & 15) << 2;
                *(float4*)&xs[r * XSS + c] = xr[it];
            }
        }
        __syncthreads();

        // issue next chunk's loads (land during compute)
        if (kc + KC < DIM) {
            #pragma unroll
            for (int it = 0; it < 4; it++) {
                int idx = tid + it * NTH;
                int r = idx >> 4, c = (idx & 15) << 2;
                wr[it] = *(const float4*)(w + (size_t)r * DIM + kc + KC + c);
            }
            #pragma unroll
            for (int it = 0; it < 7; it++) {
                int idx = tid + it * NTH;
                if (idx < XSLOTS) {
                    int r = idx >> 4, c = (idx & 15) << 2;
                    int rr = min(base + r, NTOK - 1);
                    xr[it] = *(const float4*)(x + (size_t)rr * DIM + kc + KC + c);
                }
            }
        }

        // warp-uniform branch (warps 0-5: NT=7, warps 6-7: NT=6)
        if (ts < 12) compute_chunk<7>(xs, wq4, et, row0, acc);
        else         compute_chunk<6>(xs, wq4, et, row0, acc);
    }
    __syncthreads();   // all xs reads done before lg overwrites the union

    // logits + bias -> lg
    #pragma unroll
    for (int j = 0; j < 4; j++) {
        float b = bias[et * 4 + j];
        for (int i = 0; i < nt; i++)
            lg[(row0 + i) * LGS + et * 4 + j] = acc[i][j] + b;
    }
    if (tid < 2 * NEXP) s_cnt[tid] = 0.f;
    __syncthreads();

    const int b0 = base / SEQ;
    const int t_split = min(BMT, (b0 + 1) * SEQ - base);   // batch boundary in block

    // per-token softmax (FTZ) + top-8 on SCORES, ties -> lower index (lax.top_k)
    if (tid < nval) {
        const int t = tid;
        const float* lrow = &lg[t * LGS];
        float m = -FLT_MAX;
        for (int e = 0; e < NEXP; e++) m = fmaxf(m, lrow[e]);

        float sum = 0.f;
        for (int e = 0; e < NEXP; e++) {
            float s = expf(lrow[e] - m);
            if (s < FTZ_MIN) s = 0.f;
            sum += s;
        }
        float inv_sum = 1.f / sum;

        float bv[TOPK]; int bi[TOPK];
        #pragma unroll
        for (int r = 0; r < TOPK; r++) { bv[r] = -FLT_MAX; bi[r] = 0; }

        for (int e = 0; e < NEXP; e++) {
            float s = expf(lrow[e] - m);
            if (s < FTZ_MIN) s = 0.f;
            float q = s * inv_sum;
            if (q < FTZ_MIN) q = 0.f;
            if (q > bv[TOPK - 1]) {
                int p = TOPK - 1;
                while (p > 0 && q > bv[p - 1]) {
                    bv[p] = bv[p - 1]; bi[p] = bi[p - 1]; p--;
                }
                bv[p] = q; bi[p] = e;
            }
        }
        s_max[t] = m;
        s_inv[t] = inv_sum;

        float den = 1e-20f;
        #pragma unroll
        for (int r = 0; r < TOPK; r++) den += bv[r];
        float inv = 1.f / den;

        const int token = base + t;
        const int part  = (t < t_split) ? 0 : 1;
        #pragma unroll
        for (int r = 0; r < TOPK; r++)
            out[(size_t)token * TOPK + r] = (float)bi[r];
        #pragma unroll
        for (int r = 0; r < TOPK; r++)
            out[(size_t)NTOK * TOPK + (size_t)token * TOPK + r] = bv[r] * inv;
        #pragma unroll
        for (int r = 0; r < TOPK; r++)
            atomicAdd(&s_cnt[part * NEXP + bi[r]], 1.f);
    }
    __syncthreads();

    // per-expert column sums of (flushed) softmax scores, split by batch bucket
    if (tid < NEXP) {
        const int e = tid;
        float cs0 = 0.f, cs1 = 0.f;
        for (int t = 0; t < nval; t++) {
            float s = expf(lg[t * LGS + e] - s_max[t]);
            if (s < FTZ_MIN) s = 0.f;
            float q = s * s_inv[t];
            if (q < FTZ_MIN) q = 0.f;
            if (t < t_split) cs0 += q; else cs1 += q;
        }
        atomicAdd(&g_ssum[b0 * NEXP + e], cs0);
        atomicAdd(&g_cnt [b0 * NEXP + e], s_cnt[e]);
        if (t_split < nval) {
            atomicAdd(&g_ssum[(b0 + 1) * NEXP + e], cs1);
            atomicAdd(&g_cnt [(b0 + 1) * NEXP + e], s_cnt[NEXP + e]);
        }
    }

    // ---- fused finalize: last block computes aux, then resets globals ----
    __threadfence();
    __syncthreads();
    if (tid == 0)
        s_last = (atomicAdd(&g_done, 1u) == (unsigned)(NBLK - 1));
    __syncthreads();

    if (s_last) {
        float* red = regA;                  // lg no longer needed
        // aux = mean_b sum_e (cnt/(SEQ*K/E)) * (ssum/SEQ)
        float v = (g_cnt[tid] * (1.f / 512.f)) * (g_ssum[tid] * (1.f / 4096.f));
        red[tid] = v;
        __syncthreads();
        for (int s = 128; s > 0; s >>= 1) {
            if (tid < s) red[tid] += red[tid + s];
            __syncthreads();
        }
        if (tid == 0) out[2 * NTOK * TOPK] = red[0] * (1.f / BSZ);
        // reset for next graph replay
        g_cnt[tid] = 0.f;
        g_ssum[tid] = 0.f;
        if (tid == 0) g_done = 0u;
    }
}

extern "C" void kernel_launch(void* const* d_in, const int* in_sizes, int n_in,
                              void* d_out, int out_size) {
    const float* x    = (const float*)d_in[0];   // [4,4096,2048] f32
    const float* wgt  = (const float*)d_in[1];   // [64,2048]     f32
    const float* bias = (const float*)d_in[2];   // [64]          f32
    float* out = (float*)d_out;                  // [idx 131072][w 131072][aux 1]

    gate_main<<<NBLK, NTH>>>(x, wgt, bias, out);
}